// round 13
// baseline (speedup 1.0000x reference)
#include <cuda_runtime.h>
#include <math.h>
#include <stdint.h>

#define AG    10
#define SEQ   50
#define IND   6
#define HID   64
#define OUTD  2
#define TDEC  60
#define BATCH 32768

#define NG      256   // 4*HID gate columns
#define MT      64    // batch rows per CTA
#define THREADS 256
#define AST     68    // staging row stride in floats (pad vs 64)
#define KC      16    // K-chunk rows for weight streaming
#define NBUF    2     // cp.async ring depth

// Unified staging row map: [0..5]=x/out, [6]=bias(ones), [7..70]=h0, [71..134]=h1
#define ROW_BIAS 6
#define ROW_H0   7
#define ROW_H1   71
#define STG_ROWS 136

// Logical K per section and padded (multiple of KC) row counts
#define KE0 71    // rows 0..70   (x, bias, h0)
#define KE1 129   // rows 6..134  (bias, h0, h1)
#define KD0 67    // rows 4..70   (out, bias, h0)
#define KD1 129   // rows 6..134
#define PE0 80
#define PE1 144
#define PD0 80
#define PD1 144

#define OFF_E0 0
#define OFF_E1 (PE0*NG)
#define OFF_D0 ((PE0+PE1)*NG)
#define OFF_D1 ((PE0+PE1+PD0)*NG)
#define WTOT   ((PE0+PE1+PD0+PD1)*NG)

typedef unsigned long long u64t;

// Pre-permuted, bias-folded weight scratch (gate-interleaved columns).
__device__ __align__(16) float g_W[WTOT];

// ---------------------------------------------------------------------------
// Prep kernel: build g_W. Column n = 4*j + q maps to gate row r = q*64 + j.
// Row ordering matches the unified staging layout per section.
// ---------------------------------------------------------------------------
__global__ void prep_kernel(
    const float* __restrict__ eWih0, const float* __restrict__ eWhh0,
    const float* __restrict__ ebih0, const float* __restrict__ ebhh0,
    const float* __restrict__ eWih1, const float* __restrict__ eWhh1,
    const float* __restrict__ ebih1, const float* __restrict__ ebhh1,
    const float* __restrict__ dWih0, const float* __restrict__ dWhh0,
    const float* __restrict__ dbih0, const float* __restrict__ dbhh0,
    const float* __restrict__ dWih1, const float* __restrict__ dWhh1,
    const float* __restrict__ dbih1, const float* __restrict__ dbhh1)
{
    int idx = blockIdx.x * blockDim.x + threadIdx.x;
    if (idx >= WTOT) return;
    int n    = idx & (NG - 1);
    int grow = idx >> 8;
    int r    = ((n & 3) << 6) | (n >> 2);
    float v = 0.f;
    if (grow < PE0) {                       // E0: [x(6) | bias | h0(64)]
        int row = grow;
        if      (row < 6)   v = eWih0[r * IND + row];
        else if (row == 6)  v = ebih0[r] + ebhh0[r];
        else if (row <= 70) v = eWhh0[r * HID + (row - 7)];
    } else if (grow < PE0 + PE1) {          // E1: [bias | h0(64) | h1(64)]
        int row = grow - PE0;
        if      (row == 0)   v = ebih1[r] + ebhh1[r];
        else if (row <= 64)  v = eWih1[r * HID + (row - 1)];
        else if (row <= 128) v = eWhh1[r * HID + (row - 65)];
    } else if (grow < PE0 + PE1 + PD0) {    // D0: [out(2) | bias | h0(64)]
        int row = grow - (PE0 + PE1);
        if      (row < 2)   v = dWih0[r * OUTD + row];
        else if (row == 2)  v = dbih0[r] + dbhh0[r];
        else if (row <= 66) v = dWhh0[r * HID + (row - 3)];
    } else {                                // D1: [bias | h0(64) | h1(64)]
        int row = grow - (PE0 + PE1 + PD0);
        if      (row == 0)   v = dbih1[r] + dbhh1[r];
        else if (row <= 64)  v = dWih1[r * HID + (row - 1)];
        else if (row <= 128) v = dWhh1[r * HID + (row - 65)];
    }
    g_W[idx] = v;
}

// ---------------------------------------------------------------------------
// Device helpers
// ---------------------------------------------------------------------------
__device__ __forceinline__ float sigmf(float x) {
    return __fdividef(1.f, 1.f + __expf(-x));
}
__device__ __forceinline__ float tanhf_(float x) {
    float e = __expf(2.f * x);
    return 1.f - __fdividef(2.f, e + 1.f);
}

// Packed f32x2 helpers (Blackwell double-rate fp32 path).
__device__ __forceinline__ u64t dup2(float a) {
    u64t r;
    asm("mov.b64 %0, {%1, %1};" : "=l"(r) : "f"(a));
    return r;
}
__device__ __forceinline__ void fma2(u64t& d, u64t a, u64t b) {
    asm("fma.rn.f32x2 %0, %1, %2, %3;" : "=l"(d) : "l"(a), "l"(b), "l"(d));
}
__device__ __forceinline__ float2 unpk(u64t v) {
    float2 r;
    asm("mov.b64 {%0, %1}, %2;" : "=f"(r.x), "=f"(r.y) : "l"(v));
    return r;
}

// cp.async 16B global->shared (LDGSTS), L1-bypass.
__device__ __forceinline__ void cpa16(uint32_t saddr, const void* gaddr) {
    asm volatile("cp.async.cg.shared.global [%0], [%1], 16;\n"
                 :: "r"(saddr), "l"(gaddr));
}
#define CPA_COMMIT() asm volatile("cp.async.commit_group;\n" ::: "memory")
#define CPA_WAIT(N)  asm volatile("cp.async.wait_group %0;\n" :: "n"(N) : "memory")

// One k-row of FFMA2 work.
__device__ __forceinline__ void k_iter(const float* __restrict__ Arow,
                                       const float* __restrict__ Brow,
                                       u64t (&acc)[8][4], int tm0, int tn0)
{
    float4 a0 = *(const float4*)(Arow + tm0);
    float4 a1 = *(const float4*)(Arow + tm0 + 4);
    ulonglong2 b0 = *(const ulonglong2*)(Brow + tn0);
    ulonglong2 b1 = *(const ulonglong2*)(Brow + tn0 + 4);
    u64t bp[4] = {b0.x, b0.y, b1.x, b1.y};
    float av[8] = {a0.x, a0.y, a0.z, a0.w, a1.x, a1.y, a1.z, a1.w};
    #pragma unroll
    for (int i = 0; i < 8; i++) {
        u64t ad = dup2(av[i]);
        #pragma unroll
        for (int p = 0; p < 4; p++)
            fma2(acc[i][p], ad, bp[p]);
    }
}

// GEMM: packed acc[8][4] += A[K x 64] * B[K x 256].
// B streamed via cp.async through a double-buffered 16-row SMEM ring,
// one __syncthreads per chunk (+1 tail). Safe with NBUF=2: prefetch of
// chunk c+1 overwrites chunk c-1's buffer, whose readers all passed the
// barrier at the top of iteration c.
__device__ __forceinline__ void do_gemm(const float* __restrict__ Bg, int K,
                                        const float* __restrict__ A,
                                        const float* __restrict__ Bs,
                                        uint32_t bsu,
                                        u64t (&acc)[8][4],
                                        int tid, int tm0, int tn0)
{
    const int nch = (K + KC - 1) >> 4;
    const float4* __restrict__ Bgv = (const float4*)Bg;
    const uint32_t s0 = bsu + (uint32_t)tid * 16u;

    // prologue: stage chunk 0 (1024 float4 across 256 threads = 4 each)
    #pragma unroll
    for (int e = 0; e < 4; e++)
        cpa16(s0 + (uint32_t)(e * THREADS * 16), Bgv + e * THREADS + tid);
    CPA_COMMIT();

    for (int c = 0; c < nch; c++) {
        CPA_WAIT(0);
        __syncthreads();                       // chunk c visible to all
        if (c + 1 < nch) {                     // prefetch next chunk
            uint32_t bd = (uint32_t)(((c + 1) & 1) * (KC * NG * 4));
            const float4* q = Bgv + (size_t)(c + 1) * 1024;
            #pragma unroll
            for (int e = 0; e < 4; e++)
                cpa16(s0 + bd + (uint32_t)(e * THREADS * 16), q + e * THREADS + tid);
            CPA_COMMIT();
        }
        const float* Bsc = Bs + (c & 1) * (KC * NG);
        const int kc = c * KC;
        const float* Abase = A + (size_t)kc * AST;
        if (kc + KC <= K) {                    // full 16-row chunk (hot path)
            #pragma unroll 8
            for (int kk = 0; kk < KC; kk++)
                k_iter(Abase + kk * AST, Bsc + kk * NG, acc, tm0, tn0);
        } else {                               // short tail chunk
            const int kend = K - kc;
            for (int kk = 0; kk < kend; kk++)
                k_iter(Abase + kk * AST, Bsc + kk * NG, acc, tm0, tn0);
        }
    }
    __syncthreads();   // reads of A / last buffer done before caller mutates
}

// LSTM gate update: thread owns 8 rows x 2 hidden cols; single h store into
// the unified staging buffer at row base (7 for layer0, 71 for layer1).
__device__ __forceinline__ void do_update(u64t (&acc)[8][4],
                                          float2* __restrict__ csL,
                                          float* __restrict__ stg, int rbase,
                                          int lane, int tm0)
{
    #pragma unroll
    for (int i = 0; i < 8; i++) {
        float2 cv = csL[i * THREADS];
        #pragma unroll
        for (int jj = 0; jj < 2; jj++) {
            float2 g_if = unpk(acc[i][jj * 2 + 0]);
            float2 g_go = unpk(acc[i][jj * 2 + 1]);
            float cprev = (jj == 0) ? cv.x : cv.y;
            float c = sigmf(g_if.y) * cprev + sigmf(g_if.x) * tanhf_(g_go.x);
            if (jj == 0) cv.x = c; else cv.y = c;
            float h = sigmf(g_go.y) * tanhf_(c);
            stg[(rbase + lane * 2 + jj) * AST + (tm0 + i)] = h;
        }
        csL[i * THREADS] = cv;
    }
}

#define ZERO_ACC(acc) do {                          \
    _Pragma("unroll")                               \
    for (int _i = 0; _i < 8; _i++)                  \
        _Pragma("unroll")                           \
        for (int _p = 0; _p < 4; _p++)              \
            (acc)[_i][_p] = 0ull;                   \
} while (0)

// SMEM float counts
#define SM_STG (STG_ROWS*AST)
#define SM_BS  (NBUF*KC*NG)
#define SM_CS  (2*8*THREADS*2)
#define SM_TOT (SM_STG + SM_BS + SM_CS + 130)

// ---------------------------------------------------------------------------
// Main kernel. One CTA = 64 batch rows, 8 warps; TWO CTAs co-resident per SM
// in independent barrier domains (odd CTAs staggered anti-phase) so one CTA's
// MUFU epilogue overlaps the other's FFMA2 GEMM.
// ---------------------------------------------------------------------------
__global__ void __launch_bounds__(THREADS, 2)
lstm_main(const float* __restrict__ hist, const float* __restrict__ linW,
          const float* __restrict__ linb, const float* __restrict__ start,
          float* __restrict__ out)
{
    extern __shared__ float sm[];
    float*  stg = sm;                     // [STG_ROWS][AST] unified staging
    float*  Bs  = stg + SM_STG;           // [NBUF][KC][NG]  weight ring
    float*  csf = Bs + SM_BS;             // [2][8][THREADS] float2 cell state
    float*  lw  = csf + SM_CS;            // [2][64]         lin_W
    float*  lb  = lw + 128;               // [2]             lin_b

    const int tid  = threadIdx.x;
    const int lane = tid & 31;
    const int tm0  = (tid >> 5) * 8;
    const int tn0  = lane * 8;
    const int b0   = blockIdx.x * MT;

    uint32_t bsu;
    asm("{ .reg .u64 t; cvta.to.shared.u64 t, %1; cvt.u32.u64 %0, t; }"
        : "=r"(bsu) : "l"(Bs));

    float2* cs0 = (float2*)csf + tid;               // layer-0 state
    float2* cs1 = (float2*)csf + 8 * THREADS + tid; // layer-1 state

    for (int i = tid; i < SM_STG; i += THREADS) stg[i] = 0.f;
    for (int i = tid; i < SM_CS;  i += THREADS) csf[i] = 0.f;
    if (tid < MT)  stg[ROW_BIAS * AST + tid] = 1.f;   // ones row (bias feed)
    if (tid < 128) lw[tid] = linW[tid];
    if (tid < 2)   lb[tid] = linb[tid];
    __syncthreads();

    // ---- anti-phase stagger: odd CTAs burn ~half a step on a dummy GEMM ----
    if (blockIdx.x & 1) {
        u64t dacc[8][4];
        ZERO_ACC(dacc);
        do_gemm(g_W + OFF_E1, KE1, stg + ROW_BIAS * AST, Bs, bsu, dacc,
                tid, tm0, tn0);
        float s = 0.f;
        #pragma unroll
        for (int i = 0; i < 8; i++)
            #pragma unroll
            for (int p = 0; p < 4; p++) {
                float2 v = unpk(dacc[i][p]);
                s += v.x + v.y;
            }
        if (__float_as_uint(s) == 0xdeadbeefu)      // never true; keeps FMAs
            stg[(STG_ROWS - 1) * AST] = s;
        __syncthreads();
    }

    // ---------------- encoder: 50 steps ----------------
    for (int t = 0; t < SEQ; t++) {
        if (tid < MT) {
            const float* xp = hist + (size_t)(b0 + tid) * (AG * SEQ * IND) + t * IND;
            #pragma unroll
            for (int i = 0; i < IND; i++) stg[i * AST + tid] = xp[i];
        }
        u64t acc[8][4];
        ZERO_ACC(acc);
        do_gemm(g_W + OFF_E0, KE0, stg, Bs, bsu, acc, tid, tm0, tn0);
        do_update(acc, cs0, stg, ROW_H0, lane, tm0);
        ZERO_ACC(acc);
        do_gemm(g_W + OFF_E1, KE1, stg + ROW_BIAS * AST, Bs, bsu, acc, tid, tm0, tn0);
        do_update(acc, cs1, stg, ROW_H1, lane, tm0);
        // next gemm's chunk-0 barrier orders these writes
    }

    // -------- phase switch: just drop the start token into rows 4..5 --------
    __syncthreads();
    if (tid < 2 * MT) {
        int o = tid >> 6, m = tid & 63;
        stg[(4 + o) * AST + m] = start[o];
    }
    __syncthreads();

    // ---------------- decoder: 60 steps ----------------
    for (int t = 0; t < TDEC; t++) {
        u64t acc[8][4];
        ZERO_ACC(acc);
        do_gemm(g_W + OFF_D0, KD0, stg + 4 * AST, Bs, bsu, acc, tid, tm0, tn0);
        do_update(acc, cs0, stg, ROW_H0, lane, tm0);
        ZERO_ACC(acc);
        do_gemm(g_W + OFF_D1, KD1, stg + ROW_BIAS * AST, Bs, bsu, acc, tid, tm0, tn0);
        do_update(acc, cs1, stg, ROW_H1, lane, tm0);
        __syncthreads();   // h1 writes visible to the epilogue readers
        // out = h1 @ lin_W^T + lin_b ; feed back as next x; store result
        if (tid < 2 * MT) {
            int o = tid >> 6, m = tid & 63;
            float s = lb[o];
            const float* lwo = lw + o * 64;
            #pragma unroll 8
            for (int k = 0; k < HID; k++)
                s = fmaf(lwo[k], stg[(ROW_H1 + k) * AST + m], s);
            out[(size_t)(b0 + m) * (TDEC * OUTD) + t * OUTD + o] = s;
            stg[(4 + o) * AST + m] = s;
        }
        // next gemm D0's chunk-0 barrier orders the feedback writes
    }
}

// ---------------------------------------------------------------------------
// Launch
// ---------------------------------------------------------------------------
extern "C" void kernel_launch(void* const* d_in, const int* in_sizes, int n_in,
                              void* d_out, int out_size)
{
    (void)in_sizes; (void)n_in; (void)out_size;
    const float* hist = (const float*)d_in[0];

    prep_kernel<<<(WTOT + 255) / 256, 256>>>(
        (const float*)d_in[1],  (const float*)d_in[2],
        (const float*)d_in[3],  (const float*)d_in[4],
        (const float*)d_in[5],  (const float*)d_in[6],
        (const float*)d_in[7],  (const float*)d_in[8],
        (const float*)d_in[9],  (const float*)d_in[10],
        (const float*)d_in[11], (const float*)d_in[12],
        (const float*)d_in[13], (const float*)d_in[14],
        (const float*)d_in[15], (const float*)d_in[16]);

    size_t smem = (size_t)SM_TOT * sizeof(float);
    cudaFuncSetAttribute(lstm_main, cudaFuncAttributeMaxDynamicSharedMemorySize,
                         (int)smem);
    lstm_main<<<BATCH / MT, THREADS, smem>>>(
        hist, (const float*)d_in[17], (const float*)d_in[18],
        (const float*)d_in[19], (float*)d_out);
}

// round 14
// speedup vs baseline: 1.0008x; 1.0008x over previous
#include <cuda_runtime.h>
#include <math.h>
#include <stdint.h>

#define AG    10
#define SEQ   50
#define IND   6
#define HID   64
#define OUTD  2
#define TDEC  60
#define BATCH 32768

#define NG      256   // 4*HID gate columns
#define MT      64    // batch rows per CTA
#define THREADS 256
#define AST     68    // staging row stride in floats (pad vs 64)
#define KC      16    // K-chunk rows for weight streaming
#define NBUF    2     // cp.async ring depth

// Unified staging row map: [0..5]=x/out, [6]=bias(ones), [7..70]=h0, [71..134]=h1
#define ROW_BIAS 6
#define ROW_H0   7
#define ROW_H1   71
#define STG_ROWS 136

// Logical K per section and padded (multiple of KC) row counts
#define KE0 71    // rows 0..70   (x, bias, h0)
#define KE1 129   // rows 6..134  (bias, h0, h1)
#define KD0 67    // rows 4..70   (out, bias, h0)
#define KD1 129   // rows 6..134
#define PE0 80
#define PE1 144
#define PD0 80
#define PD1 144

#define OFF_E0 0
#define OFF_E1 (PE0*NG)
#define OFF_D0 ((PE0+PE1)*NG)
#define OFF_D1 ((PE0+PE1+PD0)*NG)
#define WTOT   ((PE0+PE1+PD0+PD1)*NG)

typedef unsigned long long u64t;

// Pre-permuted, bias-folded weight scratch (gate-interleaved columns).
__device__ __align__(16) float g_W[WTOT];

// ---------------------------------------------------------------------------
// Prep kernel: build g_W. Column n = 4*j + q maps to gate row r = q*64 + j.
// Row ordering matches the unified staging layout per section.
// ---------------------------------------------------------------------------
__global__ void prep_kernel(
    const float* __restrict__ eWih0, const float* __restrict__ eWhh0,
    const float* __restrict__ ebih0, const float* __restrict__ ebhh0,
    const float* __restrict__ eWih1, const float* __restrict__ eWhh1,
    const float* __restrict__ ebih1, const float* __restrict__ ebhh1,
    const float* __restrict__ dWih0, const float* __restrict__ dWhh0,
    const float* __restrict__ dbih0, const float* __restrict__ dbhh0,
    const float* __restrict__ dWih1, const float* __restrict__ dWhh1,
    const float* __restrict__ dbih1, const float* __restrict__ dbhh1)
{
    int idx = blockIdx.x * blockDim.x + threadIdx.x;
    if (idx >= WTOT) return;
    int n    = idx & (NG - 1);
    int grow = idx >> 8;
    int r    = ((n & 3) << 6) | (n >> 2);
    float v = 0.f;
    if (grow < PE0) {                       // E0: [x(6) | bias | h0(64)]
        int row = grow;
        if      (row < 6)   v = eWih0[r * IND + row];
        else if (row == 6)  v = ebih0[r] + ebhh0[r];
        else if (row <= 70) v = eWhh0[r * HID + (row - 7)];
    } else if (grow < PE0 + PE1) {          // E1: [bias | h0(64) | h1(64)]
        int row = grow - PE0;
        if      (row == 0)   v = ebih1[r] + ebhh1[r];
        else if (row <= 64)  v = eWih1[r * HID + (row - 1)];
        else if (row <= 128) v = eWhh1[r * HID + (row - 65)];
    } else if (grow < PE0 + PE1 + PD0) {    // D0: [out(2) | bias | h0(64)]
        int row = grow - (PE0 + PE1);
        if      (row < 2)   v = dWih0[r * OUTD + row];
        else if (row == 2)  v = dbih0[r] + dbhh0[r];
        else if (row <= 66) v = dWhh0[r * HID + (row - 3)];
    } else {                                // D1: [bias | h0(64) | h1(64)]
        int row = grow - (PE0 + PE1 + PD0);
        if      (row == 0)   v = dbih1[r] + dbhh1[r];
        else if (row <= 64)  v = dWih1[r * HID + (row - 1)];
        else if (row <= 128) v = dWhh1[r * HID + (row - 65)];
    }
    g_W[idx] = v;
}

// ---------------------------------------------------------------------------
// Device helpers
// ---------------------------------------------------------------------------
__device__ __forceinline__ float sigmf(float x) {
    return __fdividef(1.f, 1.f + __expf(-x));
}
__device__ __forceinline__ float tanhf_(float x) {
    float e = __expf(2.f * x);
    return 1.f - __fdividef(2.f, e + 1.f);
}

// Packed f32x2 helpers (Blackwell double-rate fp32 path).
__device__ __forceinline__ u64t dup2(float a) {
    u64t r;
    asm("mov.b64 %0, {%1, %1};" : "=l"(r) : "f"(a));
    return r;
}
__device__ __forceinline__ void fma2(u64t& d, u64t a, u64t b) {
    asm("fma.rn.f32x2 %0, %1, %2, %3;" : "=l"(d) : "l"(a), "l"(b), "l"(d));
}
__device__ __forceinline__ float2 unpk(u64t v) {
    float2 r;
    asm("mov.b64 {%0, %1}, %2;" : "=f"(r.x), "=f"(r.y) : "l"(v));
    return r;
}

// cp.async 16B global->shared (LDGSTS), L1-bypass.
__device__ __forceinline__ void cpa16(uint32_t saddr, const void* gaddr) {
    asm volatile("cp.async.cg.shared.global [%0], [%1], 16;\n"
                 :: "r"(saddr), "l"(gaddr));
}
#define CPA_COMMIT() asm volatile("cp.async.commit_group;\n" ::: "memory")
#define CPA_WAIT(N)  asm volatile("cp.async.wait_group %0;\n" :: "n"(N) : "memory")

// One k-row of FFMA2 work.
__device__ __forceinline__ void k_iter(const float* __restrict__ Arow,
                                       const float* __restrict__ Brow,
                                       u64t (&acc)[8][4], int tm0, int tn0)
{
    float4 a0 = *(const float4*)(Arow + tm0);
    float4 a1 = *(const float4*)(Arow + tm0 + 4);
    ulonglong2 b0 = *(const ulonglong2*)(Brow + tn0);
    ulonglong2 b1 = *(const ulonglong2*)(Brow + tn0 + 4);
    u64t bp[4] = {b0.x, b0.y, b1.x, b1.y};
    float av[8] = {a0.x, a0.y, a0.z, a0.w, a1.x, a1.y, a1.z, a1.w};
    #pragma unroll
    for (int i = 0; i < 8; i++) {
        u64t ad = dup2(av[i]);
        #pragma unroll
        for (int p = 0; p < 4; p++)
            fma2(acc[i][p], ad, bp[p]);
    }
}

// GEMM: packed acc[8][4] += A[K x 64] * B[K x 256].
// B streamed via cp.async through a double-buffered 16-row SMEM ring,
// one __syncthreads per chunk (+1 tail). Safe with NBUF=2: prefetch of
// chunk c+1 overwrites chunk c-1's buffer, whose readers all passed the
// barrier at the top of iteration c.
__device__ __forceinline__ void do_gemm(const float* __restrict__ Bg, int K,
                                        const float* __restrict__ A,
                                        const float* __restrict__ Bs,
                                        uint32_t bsu,
                                        u64t (&acc)[8][4],
                                        int tid, int tm0, int tn0)
{
    const int nch = (K + KC - 1) >> 4;
    const float4* __restrict__ Bgv = (const float4*)Bg;
    const uint32_t s0 = bsu + (uint32_t)tid * 16u;

    // prologue: stage chunk 0 (1024 float4 across 256 threads = 4 each)
    #pragma unroll
    for (int e = 0; e < 4; e++)
        cpa16(s0 + (uint32_t)(e * THREADS * 16), Bgv + e * THREADS + tid);
    CPA_COMMIT();

    for (int c = 0; c < nch; c++) {
        CPA_WAIT(0);
        __syncthreads();                       // chunk c visible to all
        if (c + 1 < nch) {                     // prefetch next chunk
            uint32_t bd = (uint32_t)(((c + 1) & 1) * (KC * NG * 4));
            const float4* q = Bgv + (size_t)(c + 1) * 1024;
            #pragma unroll
            for (int e = 0; e < 4; e++)
                cpa16(s0 + bd + (uint32_t)(e * THREADS * 16), q + e * THREADS + tid);
            CPA_COMMIT();
        }
        const float* Bsc = Bs + (c & 1) * (KC * NG);
        const int kc = c * KC;
        const float* Abase = A + (size_t)kc * AST;
        if (kc + KC <= K) {                    // full 16-row chunk (hot path)
            #pragma unroll 8
            for (int kk = 0; kk < KC; kk++)
                k_iter(Abase + kk * AST, Bsc + kk * NG, acc, tm0, tn0);
        } else {                               // short tail chunk
            const int kend = K - kc;
            for (int kk = 0; kk < kend; kk++)
                k_iter(Abase + kk * AST, Bsc + kk * NG, acc, tm0, tn0);
        }
    }
    __syncthreads();   // reads of A / last buffer done before caller mutates
}

// LSTM gate update: thread owns 8 rows x 2 hidden cols; single h store into
// the unified staging buffer at row base (7 for layer0, 71 for layer1).
__device__ __forceinline__ void do_update(u64t (&acc)[8][4],
                                          float2* __restrict__ csL,
                                          float* __restrict__ stg, int rbase,
                                          int lane, int tm0)
{
    #pragma unroll
    for (int i = 0; i < 8; i++) {
        float2 cv = csL[i * THREADS];
        #pragma unroll
        for (int jj = 0; jj < 2; jj++) {
            float2 g_if = unpk(acc[i][jj * 2 + 0]);
            float2 g_go = unpk(acc[i][jj * 2 + 1]);
            float cprev = (jj == 0) ? cv.x : cv.y;
            float c = sigmf(g_if.y) * cprev + sigmf(g_if.x) * tanhf_(g_go.x);
            if (jj == 0) cv.x = c; else cv.y = c;
            float h = sigmf(g_go.y) * tanhf_(c);
            stg[(rbase + lane * 2 + jj) * AST + (tm0 + i)] = h;
        }
        csL[i * THREADS] = cv;
    }
}

#define ZERO_ACC(acc) do {                          \
    _Pragma("unroll")                               \
    for (int _i = 0; _i < 8; _i++)                  \
        _Pragma("unroll")                           \
        for (int _p = 0; _p < 4; _p++)              \
            (acc)[_i][_p] = 0ull;                   \
} while (0)

// SMEM float counts
#define SM_STG (STG_ROWS*AST)
#define SM_BS  (NBUF*KC*NG)
#define SM_CS  (2*8*THREADS*2)
#define SM_TOT (SM_STG + SM_BS + SM_CS + 130)

// ---------------------------------------------------------------------------
// Main kernel. One CTA = 64 batch rows, 8 warps; TWO CTAs co-resident per SM
// in independent barrier domains (odd CTAs staggered anti-phase) so one CTA's
// MUFU epilogue overlaps the other's FFMA2 GEMM.
// ---------------------------------------------------------------------------
__global__ void __launch_bounds__(THREADS, 2)
lstm_main(const float* __restrict__ hist, const float* __restrict__ linW,
          const float* __restrict__ linb, const float* __restrict__ start,
          float* __restrict__ out)
{
    extern __shared__ float sm[];
    float*  stg = sm;                     // [STG_ROWS][AST] unified staging
    float*  Bs  = stg + SM_STG;           // [NBUF][KC][NG]  weight ring
    float*  csf = Bs + SM_BS;             // [2][8][THREADS] float2 cell state
    float*  lw  = csf + SM_CS;            // [2][64]         lin_W
    float*  lb  = lw + 128;               // [2]             lin_b

    const int tid  = threadIdx.x;
    const int lane = tid & 31;
    const int tm0  = (tid >> 5) * 8;
    const int tn0  = lane * 8;
    const int b0   = blockIdx.x * MT;

    uint32_t bsu;
    asm("{ .reg .u64 t; cvta.to.shared.u64 t, %1; cvt.u32.u64 %0, t; }"
        : "=r"(bsu) : "l"(Bs));

    float2* cs0 = (float2*)csf + tid;               // layer-0 state
    float2* cs1 = (float2*)csf + 8 * THREADS + tid; // layer-1 state

    for (int i = tid; i < SM_STG; i += THREADS) stg[i] = 0.f;
    for (int i = tid; i < SM_CS;  i += THREADS) csf[i] = 0.f;
    if (tid < MT)  stg[ROW_BIAS * AST + tid] = 1.f;   // ones row (bias feed)
    if (tid < 128) lw[tid] = linW[tid];
    if (tid < 2)   lb[tid] = linb[tid];
    __syncthreads();

    // ---- anti-phase stagger: odd CTAs burn ~half a step on a dummy GEMM ----
    if (blockIdx.x & 1) {
        u64t dacc[8][4];
        ZERO_ACC(dacc);
        do_gemm(g_W + OFF_E1, KE1, stg + ROW_BIAS * AST, Bs, bsu, dacc,
                tid, tm0, tn0);
        float s = 0.f;
        #pragma unroll
        for (int i = 0; i < 8; i++)
            #pragma unroll
            for (int p = 0; p < 4; p++) {
                float2 v = unpk(dacc[i][p]);
                s += v.x + v.y;
            }
        if (__float_as_uint(s) == 0xdeadbeefu)      // never true; keeps FMAs
            stg[(STG_ROWS - 1) * AST] = s;
        __syncthreads();
    }

    // ---------------- encoder: 50 steps ----------------
    for (int t = 0; t < SEQ; t++) {
        if (tid < MT) {
            const float* xp = hist + (size_t)(b0 + tid) * (AG * SEQ * IND) + t * IND;
            #pragma unroll
            for (int i = 0; i < IND; i++) stg[i * AST + tid] = xp[i];
        }
        u64t acc[8][4];
        ZERO_ACC(acc);
        do_gemm(g_W + OFF_E0, KE0, stg, Bs, bsu, acc, tid, tm0, tn0);
        do_update(acc, cs0, stg, ROW_H0, lane, tm0);
        ZERO_ACC(acc);
        do_gemm(g_W + OFF_E1, KE1, stg + ROW_BIAS * AST, Bs, bsu, acc, tid, tm0, tn0);
        do_update(acc, cs1, stg, ROW_H1, lane, tm0);
        // next gemm's chunk-0 barrier orders these writes
    }

    // -------- phase switch: just drop the start token into rows 4..5 --------
    __syncthreads();
    if (tid < 2 * MT) {
        int o = tid >> 6, m = tid & 63;
        stg[(4 + o) * AST + m] = start[o];
    }
    __syncthreads();

    // ---------------- decoder: 60 steps ----------------
    for (int t = 0; t < TDEC; t++) {
        u64t acc[8][4];
        ZERO_ACC(acc);
        do_gemm(g_W + OFF_D0, KD0, stg + 4 * AST, Bs, bsu, acc, tid, tm0, tn0);
        do_update(acc, cs0, stg, ROW_H0, lane, tm0);
        ZERO_ACC(acc);
        do_gemm(g_W + OFF_D1, KD1, stg + ROW_BIAS * AST, Bs, bsu, acc, tid, tm0, tn0);
        do_update(acc, cs1, stg, ROW_H1, lane, tm0);
        __syncthreads();   // h1 writes visible to the epilogue readers
        // out = h1 @ lin_W^T + lin_b ; feed back as next x; store result
        if (tid < 2 * MT) {
            int o = tid >> 6, m = tid & 63;
            float s = lb[o];
            const float* lwo = lw + o * 64;
            #pragma unroll 8
            for (int k = 0; k < HID; k++)
                s = fmaf(lwo[k], stg[(ROW_H1 + k) * AST + m], s);
            out[(size_t)(b0 + m) * (TDEC * OUTD) + t * OUTD + o] = s;
            stg[(4 + o) * AST + m] = s;
        }
        // next gemm D0's chunk-0 barrier orders the feedback writes
    }
}

// ---------------------------------------------------------------------------
// Launch
// ---------------------------------------------------------------------------
extern "C" void kernel_launch(void* const* d_in, const int* in_sizes, int n_in,
                              void* d_out, int out_size)
{
    (void)in_sizes; (void)n_in; (void)out_size;
    const float* hist = (const float*)d_in[0];

    prep_kernel<<<(WTOT + 255) / 256, 256>>>(
        (const float*)d_in[1],  (const float*)d_in[2],
        (const float*)d_in[3],  (const float*)d_in[4],
        (const float*)d_in[5],  (const float*)d_in[6],
        (const float*)d_in[7],  (const float*)d_in[8],
        (const float*)d_in[9],  (const float*)d_in[10],
        (const float*)d_in[11], (const float*)d_in[12],
        (const float*)d_in[13], (const float*)d_in[14],
        (const float*)d_in[15], (const float*)d_in[16]);

    size_t smem = (size_t)SM_TOT * sizeof(float);
    cudaFuncSetAttribute(lstm_main, cudaFuncAttributeMaxDynamicSharedMemorySize,
                         (int)smem);
    lstm_main<<<BATCH / MT, THREADS, smem>>>(
        hist, (const float*)d_in[17], (const float*)d_in[18],
        (const float*)d_in[19], (float*)d_out);
}

// round 16
// speedup vs baseline: 2.0732x; 2.0716x over previous
#include <cuda_runtime.h>
#include <cuda_bf16.h>
#include <stdint.h>

#define AG 10
#define SEQ 50
#define IND 6
#define HID 64
#define OUTD 2
#define TDEC 60
#define BATCH 32768
#define THREADS 256
#define MT 64
#define KPAD 168
#define GB 16384                 // bytes per 16-k group (hi 8KB + lo 8KB)

#define STGH_OFF 32768           // ring: 2 x 16KB at offset 0
#define STGL_OFF (STGH_OFF + MT*KPAD*2)
#define LW_OFF   (STGL_OFF + MT*KPAD*2)
#define LB_OFF   (LW_OFF + 512)
#define SM_TOT   (LB_OFF + 16)

// Weights: 28 groups (E0:0-4, E1:5-13, D0:14-18, D1:19-27), each 16KB.
__device__ __align__(16) unsigned char g_Wb[28 * GB];

// ---------------------------------------------------------------------------
// prep: gate-permute + bias-fold + bf16 hi/lo split + B-fragment layout.
// n <-> (j,q): p=n&15, q=((p>>3)<<1)|(p&1), j=((n>>4)<<2)|((p>>1)&3), r=q*64+j.
// k-slot axis: [x/out 0-5 | bias 6 | pad 7 | h0 8-71 | h1 72-135 | pad].
// Block layout: [group][split][n=256][k=16] bf16, k-offset XOR-swizzled by n&4.
// ---------------------------------------------------------------------------
__global__ void prep(
    const float* eWih0, const float* eWhh0, const float* ebih0, const float* ebhh0,
    const float* eWih1, const float* eWhh1, const float* ebih1, const float* ebhh1,
    const float* dWih0, const float* dWhh0, const float* dbih0, const float* dbhh0,
    const float* dWih1, const float* dWhh1, const float* dbih1, const float* dbhh1)
{
    int idx = blockIdx.x * blockDim.x + threadIdx.x;
    if (idx >= 28 * 2 * 4096) return;
    int kk = idx & 15, n = (idx >> 4) & 255, s = (idx >> 12) & 1, g = idx >> 13;
    int p = n & 15;
    int q = ((p >> 3) << 1) | (p & 1);
    int j = ((n >> 4) << 2) | ((p >> 1) & 3);
    int r = q * 64 + j;
    int sec, gl;
    if (g < 5)       { sec = 0; gl = g; }
    else if (g < 14) { sec = 1; gl = g - 5; }
    else if (g < 19) { sec = 2; gl = g - 14; }
    else             { sec = 3; gl = g - 19; }
    int slot = gl * 16 + kk;
    float w = 0.f;
    if (sec == 0) {
        if (slot < 6) w = eWih0[r * IND + slot];
        else if (slot == 6) w = ebih0[r] + ebhh0[r];
        else if (slot >= 8 && slot <= 71) w = eWhh0[r * HID + slot - 8];
    } else if (sec == 1) {
        if (slot == 6) w = ebih1[r] + ebhh1[r];
        else if (slot >= 8 && slot <= 71) w = eWih1[r * HID + slot - 8];
        else if (slot >= 72 && slot <= 135) w = eWhh1[r * HID + slot - 72];
    } else if (sec == 2) {
        if (slot < 2) w = dWih0[r * OUTD + slot];
        else if (slot == 6) w = dbih0[r] + dbhh0[r];
        else if (slot >= 8 && slot <= 71) w = dWhh0[r * HID + slot - 8];
    } else {
        if (slot == 6) w = dbih1[r] + dbhh1[r];
        else if (slot >= 8 && slot <= 71) w = dWih1[r * HID + slot - 8];
        else if (slot >= 72 && slot <= 135) w = dWhh1[r * HID + slot - 72];
    }
    __nv_bfloat16 h = __float2bfloat16(w);
    if (s) h = __float2bfloat16(w - __bfloat162float(h));
    int kx = (kk * 2) ^ ((n & 4) << 2);          // bank swizzle
    *(unsigned short*)(g_Wb + (size_t)g * GB + s * 8192 + n * 32 + kx) =
        __bfloat16_as_ushort(h);
}

// ---------------------------------------------------------------------------
__device__ __forceinline__ float sigmf(float x) {
    return __fdividef(1.f, 1.f + __expf(-x));
}
__device__ __forceinline__ float tanhf_(float x) {
    float e = __expf(2.f * x);
    return 1.f - __fdividef(2.f, e + 1.f);
}
__device__ __forceinline__ uint32_t smem_u32(const void* p) {
    uint32_t a;
    asm("{ .reg .u64 t; cvta.to.shared.u64 t, %1; cvt.u32.u64 %0, t; }" : "=r"(a) : "l"(p));
    return a;
}
__device__ __forceinline__ void cpa16(uint32_t s, const void* g) {
    asm volatile("cp.async.cg.shared.global [%0], [%1], 16;" :: "r"(s), "l"(g));
}
#define CPA_COMMIT() asm volatile("cp.async.commit_group;" ::: "memory")
#define CPA_WAIT0()  asm volatile("cp.async.wait_group 0;" ::: "memory")

__device__ __forceinline__ void mma_bf16(float* d, const uint32_t* a, const uint32_t* b) {
    asm volatile("mma.sync.aligned.m16n8k16.row.col.f32.bf16.bf16.f32 "
        "{%0,%1,%2,%3},{%4,%5,%6,%7},{%8,%9},{%0,%1,%2,%3};"
        : "+f"(d[0]), "+f"(d[1]), "+f"(d[2]), "+f"(d[3])
        : "r"(a[0]), "r"(a[1]), "r"(a[2]), "r"(a[3]), "r"(b[0]), "r"(b[1]));
}

__device__ __forceinline__ void split_st(__nv_bfloat16* H, __nv_bfloat16* L,
                                         int off, float v) {
    __nv_bfloat16 h = __float2bfloat16(v);
    H[off] = h;
    L[off] = __float2bfloat16(v - __bfloat162float(h));
}

// GEMM: acc[2][8][4] = A[64 x 16*ng] * B^T, warp tile m32 x n64, bf16 3-pass.
// B streamed via cp.async through a 2-slot 16KB ring (round-11 cadence).
__device__ __forceinline__ void do_gemm(const unsigned char* gW, int ng,
        const __nv_bfloat16* stgH, const __nv_bfloat16* stgL,
        const unsigned char* smb, uint32_t ringu,
        float (&acc)[2][8][4], int tid, int lane, int m0, int n0)
{
    #pragma unroll
    for (int a = 0; a < 2; a++)
        #pragma unroll
        for (int b = 0; b < 8; b++)
            #pragma unroll
            for (int c = 0; c < 4; c++) acc[a][b][c] = 0.f;
    const int r = lane >> 2, c2 = (lane & 3) * 2;

    #pragma unroll
    for (int e = 0; e < 4; e++)
        cpa16(ringu + (e * THREADS + tid) * 16, gW + (e * THREADS + tid) * 16);
    CPA_COMMIT();

    for (int g = 0; g < ng; g++) {
        CPA_WAIT0();
        __syncthreads();
        if (g + 1 < ng) {
            const unsigned char* src = gW + (size_t)(g + 1) * GB;
            uint32_t d = ringu + ((g + 1) & 1) * GB;
            #pragma unroll
            for (int e = 0; e < 4; e++)
                cpa16(d + (e * THREADS + tid) * 16, src + (e * THREADS + tid) * 16);
            CPA_COMMIT();
        }
        const int kb = g * 16;
        uint32_t ah[2][4], al[2][4];
        #pragma unroll
        for (int mt = 0; mt < 2; mt++) {
            int mb = m0 + mt * 16 + r;
            ah[mt][0] = *(const uint32_t*)(stgH + mb * KPAD + kb + c2);
            ah[mt][1] = *(const uint32_t*)(stgH + (mb + 8) * KPAD + kb + c2);
            ah[mt][2] = *(const uint32_t*)(stgH + mb * KPAD + kb + c2 + 8);
            ah[mt][3] = *(const uint32_t*)(stgH + (mb + 8) * KPAD + kb + c2 + 8);
            al[mt][0] = *(const uint32_t*)(stgL + mb * KPAD + kb + c2);
            al[mt][1] = *(const uint32_t*)(stgL + (mb + 8) * KPAD + kb + c2);
            al[mt][2] = *(const uint32_t*)(stgL + mb * KPAD + kb + c2 + 8);
            al[mt][3] = *(const uint32_t*)(stgL + (mb + 8) * KPAD + kb + c2 + 8);
        }
        const unsigned char* bs = smb + (g & 1) * GB;
        #pragma unroll
        for (int nt = 0; nt < 8; nt++) {
            int n = n0 + nt * 8 + r;
            int xr = (n & 4) << 2;
            const unsigned char* bp = bs + n * 32;
            uint32_t bh[2], bl[2];
            bh[0] = *(const uint32_t*)(bp + ((c2 * 2) ^ xr));
            bh[1] = *(const uint32_t*)(bp + ((c2 * 2 + 16) ^ xr));
            bl[0] = *(const uint32_t*)(bp + 8192 + ((c2 * 2) ^ xr));
            bl[1] = *(const uint32_t*)(bp + 8192 + ((c2 * 2 + 16) ^ xr));
            #pragma unroll
            for (int mt = 0; mt < 2; mt++) {
                mma_bf16(acc[mt][nt], ah[mt], bh);
                mma_bf16(acc[mt][nt], al[mt], bh);
                mma_bf16(acc[mt][nt], ah[mt], bl);
            }
        }
    }
    __syncthreads();
}

// Epilogue: thread owns 16 (m,j) cells with full i,f,g,o quads.
__device__ __forceinline__ void epi(float (&acc)[2][8][4], float* cst,
        __nv_bfloat16* stgH, __nv_bfloat16* stgL, int kh, int lane, int m0, int wn)
{
    const int r = lane >> 2, jl = lane & 3;
    #pragma unroll
    for (int mt = 0; mt < 2; mt++)
        #pragma unroll
        for (int rr = 0; rr < 2; rr++) {
            int m = m0 + mt * 16 + rr * 8 + r;
            #pragma unroll
            for (int u = 0; u < 4; u++) {
                float gi = acc[mt][2 * u][rr * 2 + 0];
                float gf = acc[mt][2 * u][rr * 2 + 1];
                float gg = acc[mt][2 * u + 1][rr * 2 + 0];
                float go = acc[mt][2 * u + 1][rr * 2 + 1];
                int ci = (mt * 2 + rr) * 4 + u;
                float cc = sigmf(gf) * cst[ci] + sigmf(gi) * tanhf_(gg);
                cst[ci] = cc;
                float h = sigmf(go) * tanhf_(cc);
                int j = wn * 16 + u * 4 + jl;
                split_st(stgH, stgL, m * KPAD + kh + j, h);
            }
        }
}

// ---------------------------------------------------------------------------
__global__ void __launch_bounds__(THREADS, 2)
lstm_mma(const float* __restrict__ hist, const float* __restrict__ linW,
         const float* __restrict__ linb, const float* __restrict__ start,
         float* __restrict__ out)
{
    extern __shared__ __align__(16) unsigned char sm[];
    __nv_bfloat16* stgH = (__nv_bfloat16*)(sm + STGH_OFF);
    __nv_bfloat16* stgL = (__nv_bfloat16*)(sm + STGL_OFF);
    float* lw = (float*)(sm + LW_OFF);
    float* lb = (float*)(sm + LB_OFF);
    uint32_t ringu = smem_u32(sm);

    const int tid = threadIdx.x, lane = tid & 31, wid = tid >> 5;
    const int m0 = (wid & 1) * 32, wn = wid >> 1, n0 = wn * 64;
    const int b0 = blockIdx.x * MT;

    for (int i = tid; i < MT * KPAD; i += THREADS) {
        stgH[i] = __float2bfloat16(0.f);
        stgL[i] = __float2bfloat16(0.f);
    }
    if (tid < 128) lw[tid] = linW[tid];
    if (tid < 2)   lb[tid] = linb[tid];
    __syncthreads();
    if (tid < MT) stgH[tid * KPAD + 6] = __float2bfloat16(1.f);   // bias feed

    float c0[16], c1[16];
    #pragma unroll
    for (int i = 0; i < 16; i++) { c0[i] = 0.f; c1[i] = 0.f; }
    float acc[2][8][4];

    // ---------------- encoder ----------------
    for (int t = 0; t < SEQ; t++) {
        if (tid < MT) {
            const float* xp = hist + (size_t)(b0 + tid) * (AG * SEQ * IND) + t * IND;
            #pragma unroll
            for (int i = 0; i < IND; i++)
                split_st(stgH, stgL, tid * KPAD + i, xp[i]);
        }
        do_gemm(g_Wb,          5, stgH, stgL, sm, ringu, acc, tid, lane, m0, n0);
        epi(acc, c0, stgH, stgL, 8,  lane, m0, wn);
        do_gemm(g_Wb + 5 * GB, 9, stgH, stgL, sm, ringu, acc, tid, lane, m0, n0);
        epi(acc, c1, stgH, stgL, 72, lane, m0, wn);
    }

    // ---------------- start token ----------------
    __syncthreads();
    if (tid < MT) {
        split_st(stgH, stgL, tid * KPAD + 0, start[0]);
        split_st(stgH, stgL, tid * KPAD + 1, start[1]);
    }

    // ---------------- decoder ----------------
    for (int t = 0; t < TDEC; t++) {
        do_gemm(g_Wb + 14 * GB, 5, stgH, stgL, sm, ringu, acc, tid, lane, m0, n0);
        epi(acc, c0, stgH, stgL, 8,  lane, m0, wn);
        do_gemm(g_Wb + 19 * GB, 9, stgH, stgL, sm, ringu, acc, tid, lane, m0, n0);
        epi(acc, c1, stgH, stgL, 72, lane, m0, wn);
        __syncthreads();
        if (tid < 128) {
            int o = tid >> 6, m = tid & 63;
            float s = lb[o];
            const float* lwo = lw + o * 64;
            #pragma unroll 8
            for (int k = 0; k < HID; k++)
                s = fmaf(lwo[k], __bfloat162float(stgH[m * KPAD + 72 + k])
                               + __bfloat162float(stgL[m * KPAD + 72 + k]), s);
            out[(size_t)(b0 + m) * (TDEC * OUTD) + t * OUTD + o] = s;
            split_st(stgH, stgL, m * KPAD + o, s);
        }
        // next gemm's first barrier orders the feedback writes
    }
}

// ---------------------------------------------------------------------------
extern "C" void kernel_launch(void* const* d_in, const int* in_sizes, int n_in,
                              void* d_out, int out_size)
{
    (void)in_sizes; (void)n_in; (void)out_size;
    prep<<<(28 * 2 * 4096 + 255) / 256, 256>>>(
        (const float*)d_in[1],  (const float*)d_in[2],
        (const float*)d_in[3],  (const float*)d_in[4],
        (const float*)d_in[5],  (const float*)d_in[6],
        (const float*)d_in[7],  (const float*)d_in[8],
        (const float*)d_in[9],  (const float*)d_in[10],
        (const float*)d_in[11], (const float*)d_in[12],
        (const float*)d_in[13], (const float*)d_in[14],
        (const float*)d_in[15], (const float*)d_in[16]);

    cudaFuncSetAttribute(lstm_mma, cudaFuncAttributeMaxDynamicSharedMemorySize,
                         SM_TOT);
    lstm_mma<<<BATCH / MT, THREADS, SM_TOT>>>(
        (const float*)d_in[0], (const float*)d_in[17], (const float*)d_in[18],
        (const float*)d_in[19], (float*)d_out);
}